// round 1
// baseline (speedup 1.0000x reference)
#include <cuda_runtime.h>
#include <math_constants.h>

// Problem constants
#define NT 65536   // B*T rows
#define D  256     // embedding dim
#define NE 1024    // codebook size
#define MT 64      // rows per block
#define KT 32      // k-chunk
#define ZPAD 68    // padded row stride (floats) for smem tiles (keeps 16B align)

// Dynamic smem layout (floats unless noted):
//   zsT   [D][ZPAD]    : transposed z tile        -> 256*68 = 17408
//   cbs   [KT][ZPAD]   : codebook k-chunk         -> 32*68  = 2176
//   z2s   [MT]         : row squared norms (f32)  -> 64
//   bestd [MT]         : running min dist         -> 64
//   besti [MT] (int)   : running argmin           -> 64
//   red   [256] double : loss reduction           -> 2048 B
#define SMEM_FLOATS (256*ZPAD + KT*ZPAD + MT + MT + MT)
#define SMEM_BYTES  (SMEM_FLOATS*4 + 256*8)

__device__ double g_loss_acc;
__device__ float  g_e2[NE];

// ---------------------------------------------------------------------------
// Prep: codebook squared norms (fp64 accumulate) + zero loss accumulator
// ---------------------------------------------------------------------------
__global__ void vq_prep_kernel(const float* __restrict__ cb) {
    int c = blockIdx.x * blockDim.x + threadIdx.x;
    if (c == 0) g_loss_acc = 0.0;
    if (c < NE) {
        const float* row = cb + (size_t)c * D;
        double s = 0.0;
        #pragma unroll 8
        for (int k = 0; k < D; k++) {
            double v = (double)row[k];
            s += v * v;
        }
        g_e2[c] = (float)s;
    }
}

// ---------------------------------------------------------------------------
// Main: per 64-row block — fp32 GEMM vs all 1024 codes, running argmin,
// then gather z_q, write indices, accumulate loss.
// ---------------------------------------------------------------------------
__global__ __launch_bounds__(256) void vq_main_kernel(
    const float* __restrict__ z,
    const float* __restrict__ cb,
    float* __restrict__ out)
{
    extern __shared__ float sm[];
    float* zsT   = sm;                       // [D][ZPAD]
    float* cbs   = zsT + 256 * ZPAD;         // [KT][ZPAD]
    float* z2s   = cbs + KT * ZPAD;          // [MT]
    float* bestd = z2s + MT;                 // [MT]
    int*   besti = (int*)(bestd + MT);       // [MT]
    double* red  = (double*)(besti + MT);    // [256]

    const int tid = threadIdx.x;
    const int m0  = blockIdx.x * MT;

    // ---- Stage z tile transposed: zsT[k][r] = z[m0+r][k] ----
    #pragma unroll
    for (int it = 0; it < (MT * D) / 256; it++) {
        int idx = it * 256 + tid;
        int r = idx >> 8;          // / 256
        int k = idx & 255;
        zsT[k * ZPAD + r] = z[(size_t)(m0 + r) * D + k];
    }
    __syncthreads();

    // ---- Row squared norms (fp64), init running best ----
    if (tid < MT) {
        double s = 0.0;
        #pragma unroll 8
        for (int k = 0; k < D; k++) {
            double v = (double)zsT[k * ZPAD + tid];
            s += v * v;
        }
        z2s[tid]   = (float)s;
        bestd[tid] = CUDART_INF_F;
        besti[tid] = 0;
    }
    __syncthreads();

    const int ty = tid >> 4;          // 0..15 -> row group
    const int tx = tid & 15;          // 0..15 -> col group
    const int rbase = ty * 4;
    const int cbase = tx * 4;

    for (int n0 = 0; n0 < NE; n0 += MT) {
        float acc[4][4];
        #pragma unroll
        for (int i = 0; i < 4; i++)
            #pragma unroll
            for (int j = 0; j < 4; j++) acc[i][j] = 0.0f;

        for (int k0 = 0; k0 < D; k0 += KT) {
            // Stage codebook chunk: cbs[kk][c] = cb[n0+c][k0+kk]
            #pragma unroll
            for (int it = 0; it < (MT * KT) / 256; it++) {
                int idx = it * 256 + tid;
                int c  = idx >> 5;    // / KT
                int kk = idx & 31;
                cbs[kk * ZPAD + c] = cb[(size_t)(n0 + c) * D + (k0 + kk)];
            }
            __syncthreads();

            #pragma unroll
            for (int kk = 0; kk < KT; kk++) {
                float4 a = *reinterpret_cast<const float4*>(&zsT[(k0 + kk) * ZPAD + rbase]);
                float4 b = *reinterpret_cast<const float4*>(&cbs[kk * ZPAD + cbase]);
                acc[0][0] = fmaf(a.x, b.x, acc[0][0]);
                acc[0][1] = fmaf(a.x, b.y, acc[0][1]);
                acc[0][2] = fmaf(a.x, b.z, acc[0][2]);
                acc[0][3] = fmaf(a.x, b.w, acc[0][3]);
                acc[1][0] = fmaf(a.y, b.x, acc[1][0]);
                acc[1][1] = fmaf(a.y, b.y, acc[1][1]);
                acc[1][2] = fmaf(a.y, b.z, acc[1][2]);
                acc[1][3] = fmaf(a.y, b.w, acc[1][3]);
                acc[2][0] = fmaf(a.z, b.x, acc[2][0]);
                acc[2][1] = fmaf(a.z, b.y, acc[2][1]);
                acc[2][2] = fmaf(a.z, b.z, acc[2][2]);
                acc[2][3] = fmaf(a.z, b.w, acc[2][3]);
                acc[3][0] = fmaf(a.w, b.x, acc[3][0]);
                acc[3][1] = fmaf(a.w, b.y, acc[3][1]);
                acc[3][2] = fmaf(a.w, b.z, acc[3][2]);
                acc[3][3] = fmaf(a.w, b.w, acc[3][3]);
            }
            __syncthreads();
        }

        // Distances (replicate reference rounding: (z2 - 2*dot) + e2),
        // per-thread argmin over 4 codes, shfl-reduce across 16 tx lanes.
        #pragma unroll
        for (int i = 0; i < 4; i++) {
            int r = rbase + i;
            float z2 = z2s[r];
            float dmin = CUDART_INF_F;
            int   imin = 0x7fffffff;
            #pragma unroll
            for (int j = 0; j < 4; j++) {
                int c = n0 + cbase + j;
                float t = z2 - 2.0f * acc[i][j];
                float dd = t + g_e2[c];
                if (dd < dmin) { dmin = dd; imin = c; }   // ascending c -> first-min kept
            }
            #pragma unroll
            for (int off = 1; off < 16; off <<= 1) {
                float od = __shfl_xor_sync(0xffffffffu, dmin, off);
                int   oi = __shfl_xor_sync(0xffffffffu, imin, off);
                if (od < dmin || (od == dmin && oi < imin)) { dmin = od; imin = oi; }
            }
            if (tx == 0) {
                // strict < keeps earlier (lower-index) tile on ties
                if (dmin < bestd[r]) { bestd[r] = dmin; besti[r] = imin; }
            }
        }
        __syncthreads();
    }

    // ---- Epilogue: gather z_q, write output, accumulate loss (fp64) ----
    double lsum = 0.0;
    #pragma unroll
    for (int it = 0; it < (MT * D) / 256; it++) {
        int idx = it * 256 + tid;
        int r = idx >> 8;
        int k = idx & 255;
        int row = m0 + r;
        float e  = cb[(size_t)besti[r] * D + k];
        out[(size_t)row * D + k] = e;               // z_q_st == z_q numerically
        float df = e - zsT[k * ZPAD + r];
        lsum += (double)df * (double)df;
    }
    if (tid < MT) {
        // indices output (as float), after z_q block and the loss scalar
        out[(size_t)NT * D + 1 + (m0 + tid)] = (float)besti[tid];
    }

    red[tid] = lsum;
    __syncthreads();
    #pragma unroll
    for (int s = 128; s > 0; s >>= 1) {
        if (tid < s) red[tid] += red[tid + s];
        __syncthreads();
    }
    if (tid == 0) atomicAdd(&g_loss_acc, red[0]);
}

// ---------------------------------------------------------------------------
// Finalize loss: loss = mean(d2) + 0.25*mean(d2) = 1.25 * sum / (NT*D)
// ---------------------------------------------------------------------------
__global__ void vq_loss_kernel(float* __restrict__ out) {
    out[(size_t)NT * D] = (float)(1.25 * g_loss_acc / ((double)NT * (double)D));
}

// ---------------------------------------------------------------------------
extern "C" void kernel_launch(void* const* d_in, const int* in_sizes, int n_in,
                              void* d_out, int out_size) {
    const float* z;
    const float* cb;
    // Defensive input identification by size: z has NT*D elements, codebook NE*D.
    if (in_sizes[0] == NT * D) {
        z  = (const float*)d_in[0];
        cb = (const float*)d_in[1];
    } else {
        z  = (const float*)d_in[1];
        cb = (const float*)d_in[0];
    }
    float* out = (float*)d_out;

    cudaFuncSetAttribute(vq_main_kernel,
                         cudaFuncAttributeMaxDynamicSharedMemorySize, SMEM_BYTES);

    vq_prep_kernel<<<4, 256>>>(cb);
    vq_main_kernel<<<NT / MT, 256, SMEM_BYTES>>>(z, cb, out);
    vq_loss_kernel<<<1, 1>>>(out);
}